// round 4
// baseline (speedup 1.0000x reference)
#include <cuda_runtime.h>
#include <cuda_bf16.h>
#include <cstdint>

// Problem constants
#define NB    32
#define CIN   128
#define HH    112
#define WW    112
#define COUT  256

// Tiling
#define OC_TILE 128     // output channels per CTA
#define TH      8       // output rows per CTA
#define TW      16      // output cols per CTA
#define CK      8       // input channels per smem chunk
#define ISTRIDE 20      // padded smem row stride (float4-aligned, low bank conflict)
#define ICH     (10 * ISTRIDE)   // per-channel smem footprint (10 rows incl. halo)

// Transposed weights: [c][tap][oc] = [128][9][256]
__device__ float g_wT[CIN * 9 * COUT];

// ---------------------------------------------------------------------------
// f32x2 helpers (packed two-wide fp32 FMA — doubles FFMA throughput on sm_103a)
// ---------------------------------------------------------------------------
__device__ __forceinline__ unsigned long long pk2(float lo, float hi) {
    unsigned long long r;
    asm("mov.b64 %0, {%1, %2};" : "=l"(r)
        : "r"(__float_as_uint(lo)), "r"(__float_as_uint(hi)));
    return r;
}
__device__ __forceinline__ void upk2(unsigned long long v, float& lo, float& hi) {
    unsigned int a, b;
    asm("mov.b64 {%0, %1}, %2;" : "=r"(a), "=r"(b) : "l"(v));
    lo = __uint_as_float(a);
    hi = __uint_as_float(b);
}
__device__ __forceinline__ void fma2(unsigned long long& d,
                                     unsigned long long a,
                                     unsigned long long b) {
    asm("fma.rn.f32x2 %0, %1, %2, %0;" : "+l"(d) : "l"(a), "l"(b));
}

// ---------------------------------------------------------------------------
// Kernel 1: transpose weight (O,C,3,3) -> g_wT[(c*9+tap)*256 + o]
// ---------------------------------------------------------------------------
__global__ void wtrans_kernel(const float* __restrict__ w) {
    int j = blockIdx.x * blockDim.x + threadIdx.x;  // 0 .. 128*9*256-1
    if (j < CIN * 9 * COUT) {
        int oc  = j & (COUT - 1);
        int ct  = j >> 8;          // c*9 + tap
        int c   = ct / 9;
        int tap = ct - c * 9;
        g_wT[j] = w[(oc * CIN + c) * 9 + tap];
    }
}

// ---------------------------------------------------------------------------
// Kernel 2: direct conv, register-tiled, f32x2 FMAs
// grid = (14*7, NB, COUT/OC_TILE), block = 256
// ---------------------------------------------------------------------------
__global__ __launch_bounds__(256, 2)
void conv3x3_kernel(const float* __restrict__ in,
                    const float* __restrict__ bias,
                    float* __restrict__ out) {
    __shared__ float wsh[CK * 9 * OC_TILE];   // [c_local*9+tap][oc] 36.9 KB
    __shared__ float ish[CK * ICH];           // padded input patch   6.4 KB

    const int tid = threadIdx.x;
    const int tx  = tid & 15;        // pixel block
    const int ty  = tid >> 4;        // oc block (8 oc each)
    const int bh  = (tx >> 2) << 1;  // 0,2,4,6
    const int bw  = (tx & 3) << 2;   // 0,4,8,12

    const int n      = blockIdx.y;
    const int ocBase = blockIdx.z * OC_TILE;
    const int h0     = (blockIdx.x / 7) * TH;
    const int w0     = (blockIdx.x % 7) * TW;

    // 32 packed accumulators: acc[oc_pair][dy*4+dx], init with bias
    unsigned long long acc[4][8];
#pragma unroll
    for (int p = 0; p < 4; ++p) {
        const int oc = ocBase + ty * 8 + 2 * p;
        const unsigned long long b = pk2(bias[oc], bias[oc + 1]);
#pragma unroll
        for (int q = 0; q < 8; ++q) acc[p][q] = b;
    }

    const float4* wT4 = reinterpret_cast<const float4*>(g_wT);
    const float*  inb = in + (size_t)n * CIN * HH * WW;

#pragma unroll 1
    for (int cBase = 0; cBase < CIN; cBase += CK) {
        __syncthreads();

        // ---- stage weights: rows [cBase*9, cBase*9+72) x 128 oc, coalesced ----
        {
            const int base4 = cBase * 9 * (COUT / 4) + (ocBase >> 2);
#pragma unroll
            for (int k = 0; k < 9; ++k) {          // 9*256 = 2304 float4 total
                const int i = tid + k * 256;
                const int r = i >> 5;              // row 0..71
                const int q = i & 31;              // oc-quad 0..31
                reinterpret_cast<float4*>(wsh)[i] = wT4[base4 + r * (COUT / 4) + q];
            }
        }

        // ---- stage input patch: CK x 10 x 18 with zero halo ----
#pragma unroll 1
        for (int i = tid; i < CK * 10 * 18; i += 256) {
            const int x = i % 18;
            const int y = (i / 18) % 10;
            const int c = i / 180;
            const int gy = h0 - 1 + y;
            const int gx = w0 - 1 + x;
            float v = 0.0f;
            if (gy >= 0 && gy < HH && gx >= 0 && gx < WW)
                v = inb[((size_t)(cBase + c) * HH + gy) * WW + gx];
            ish[c * ICH + y * ISTRIDE + x] = v;
        }
        __syncthreads();

        // ---- compute: 288 FFMA2 per channel per thread ----
#pragma unroll 1
        for (int c = 0; c < CK; ++c) {
#pragma unroll
            for (int kh = 0; kh < 3; ++kh) {
#pragma unroll
                for (int dy = 0; dy < 2; ++dy) {
                    const float* ip = &ish[c * ICH + (bh + dy + kh) * ISTRIDE + bw];
                    const float4 a4 = *reinterpret_cast<const float4*>(ip);
                    const float2 a2 = *reinterpret_cast<const float2*>(ip + 4);
                    unsigned long long iv[6];
                    iv[0] = pk2(a4.x, a4.x);
                    iv[1] = pk2(a4.y, a4.y);
                    iv[2] = pk2(a4.z, a4.z);
                    iv[3] = pk2(a4.w, a4.w);
                    iv[4] = pk2(a2.x, a2.x);
                    iv[5] = pk2(a2.y, a2.y);
#pragma unroll
                    for (int kw = 0; kw < 3; ++kw) {
                        const unsigned long long* wp =
                            reinterpret_cast<const unsigned long long*>(
                                &wsh[(c * 9 + kh * 3 + kw) * OC_TILE + ty * 8]);
                        const unsigned long long w0v = wp[0];
                        const unsigned long long w1v = wp[1];
                        const unsigned long long w2v = wp[2];
                        const unsigned long long w3v = wp[3];
#pragma unroll
                        for (int dx = 0; dx < 4; ++dx) {
                            const int q = dy * 4 + dx;
                            const unsigned long long b = iv[kw + dx];
                            fma2(acc[0][q], w0v, b);
                            fma2(acc[1][q], w1v, b);
                            fma2(acc[2][q], w2v, b);
                            fma2(acc[3][q], w3v, b);
                        }
                    }
                }
            }
        }
    }

    // ---- epilogue: unpack and store (16x STG.128) ----
#pragma unroll
    for (int p = 0; p < 4; ++p) {
        const int oc = ocBase + ty * 8 + 2 * p;
#pragma unroll
        for (int dy = 0; dy < 2; ++dy) {
            float e0, e1, e2, e3, o0, o1, o2, o3;
            upk2(acc[p][dy * 4 + 0], e0, o0);
            upk2(acc[p][dy * 4 + 1], e1, o1);
            upk2(acc[p][dy * 4 + 2], e2, o2);
            upk2(acc[p][dy * 4 + 3], e3, o3);
            const int h = h0 + bh + dy;
            const size_t base =
                (((size_t)n * COUT + oc) * HH + h) * WW + (w0 + bw);
            *reinterpret_cast<float4*>(&out[base]) = make_float4(e0, e1, e2, e3);
            *reinterpret_cast<float4*>(&out[base + (size_t)HH * WW]) =
                make_float4(o0, o1, o2, o3);
        }
    }
}

// ---------------------------------------------------------------------------
// Launch
// ---------------------------------------------------------------------------
extern "C" void kernel_launch(void* const* d_in, const int* in_sizes, int n_in,
                              void* d_out, int out_size) {
    const float* input  = (const float*)d_in[0];   // (32,128,112,112)
    const float* weight = (const float*)d_in[1];   // (256,128,3,3)
    const float* bias   = (const float*)d_in[2];   // (256,)
    float* out = (float*)d_out;                    // (32,256,112,112)

    wtrans_kernel<<<(CIN * 9 * COUT + 255) / 256, 256>>>(weight);

    dim3 grid(14 * 7, NB, COUT / OC_TILE);
    conv3x3_kernel<<<grid, 256>>>(input, bias, out);
}

// round 6
// speedup vs baseline: 2.6797x; 2.6797x over previous
#include <cuda_runtime.h>
#include <cuda_bf16.h>
#include <cstdint>

// Problem constants
#define NB    32
#define CIN   128
#define HH    112
#define WW    112
#define COUT  256
#define TH    8
#define TW    16

// SMEM layout (dynamic)
#define A_TILE   16384              // 128 oc x 64 c bf16, SW128-swizzled
#define P_CELL   144                // bytes per (y,x) cell: 64ch*2B + 16B pad
#define P_BYTES  (180 * P_CELL)     // 10*18 cells = 25920 B
#define S_AHI    0
#define S_ALO    16384
#define S_PHI    32768
#define S_PLO    (32768 + P_BYTES)
#define S_TOTAL  (32768 + 2 * P_BYTES)   // 84608 -> 2 CTAs/SM

// Pre-split, pre-swizzled weights: [ocg(2)][cblk(2)][tap(9)] x {hi,lo} 16KB tiles
__device__ unsigned char g_wA[2 * 2 * 9 * 2 * A_TILE];   // 1.125 MB

// ---------------------------------------------------------------------------
// Helpers
// ---------------------------------------------------------------------------
__device__ __forceinline__ uint32_t swz128(uint32_t off) {
    return off ^ ((off >> 3) & 0x70);
}
__device__ __forceinline__ uint32_t smem_u32(const void* p) {
    uint32_t a;
    asm("{ .reg .u64 t; cvta.to.shared.u64 t, %1; cvt.u32.u64 %0, t; }"
        : "=r"(a) : "l"(p));
    return a;
}
__device__ __forceinline__ void ldsm4(uint32_t* r, uint32_t addr) {
    asm volatile("ldmatrix.sync.aligned.m8n8.x4.shared.b16 {%0,%1,%2,%3}, [%4];"
                 : "=r"(r[0]), "=r"(r[1]), "=r"(r[2]), "=r"(r[3]) : "r"(addr));
}
__device__ __forceinline__ void mma16816(float* d, const uint32_t* a,
                                         const uint32_t* b) {
    asm volatile(
        "mma.sync.aligned.m16n8k16.row.col.f32.bf16.bf16.f32 "
        "{%0,%1,%2,%3}, {%4,%5,%6,%7}, {%8,%9}, {%0,%1,%2,%3};"
        : "+f"(d[0]), "+f"(d[1]), "+f"(d[2]), "+f"(d[3])
        : "r"(a[0]), "r"(a[1]), "r"(a[2]), "r"(a[3]), "r"(b[0]), "r"(b[1]));
}
__device__ __forceinline__ void cpasync16(uint32_t dst, const void* src) {
    asm volatile("cp.async.cg.shared.global [%0], [%1], 16;"
                 :: "r"(dst), "l"(src) : "memory");
}
__device__ __forceinline__ void split_bf16(float v, __nv_bfloat16& h,
                                           __nv_bfloat16& l) {
    h = __float2bfloat16_rn(v);
    float hf = __uint_as_float((uint32_t)__bfloat16_as_ushort(h) << 16);
    l = __float2bfloat16_rn(v - hf);
}

// ---------------------------------------------------------------------------
// Kernel 1: split weights into bf16 hi/lo tiles [ocg][cblk][tap], swizzled.
// Tile layout: row = oc_local (128B rows of 64 bf16), SW128 swizzle.
// ---------------------------------------------------------------------------
__global__ void wprep_kernel(const float* __restrict__ w) {
    int j = blockIdx.x * blockDim.x + threadIdx.x;   // 256 oc * 9 tap * 64 cpair
    if (j >= 256 * 9 * 64) return;
    int cpair = j & 63;                 // c = 2*cpair over full 128
    int tap   = (j >> 6) % 9;
    int oc    = j / 576;
    int c     = cpair * 2;
    int ocg   = oc >> 7, ocl = oc & 127;
    int cblk  = c >> 6,  cl  = c & 63;

    float w0 = w[((size_t)oc * CIN + c) * 9 + tap];
    float w1 = w[((size_t)oc * CIN + c + 1) * 9 + tap];
    __nv_bfloat16 h0, l0, h1, l1;
    split_bf16(w0, h0, l0);
    split_bf16(w1, h1, l1);
    uint32_t hi = (uint32_t)__bfloat16_as_ushort(h0) |
                  ((uint32_t)__bfloat16_as_ushort(h1) << 16);
    uint32_t lo = (uint32_t)__bfloat16_as_ushort(l0) |
                  ((uint32_t)__bfloat16_as_ushort(l1) << 16);

    size_t base = (size_t)(((ocg * 2 + cblk) * 9 + tap)) * (2 * A_TILE);
    uint32_t off = swz128((uint32_t)(ocl * 128 + cl * 2));
    *(uint32_t*)(g_wA + base + off)          = hi;
    *(uint32_t*)(g_wA + base + A_TILE + off) = lo;
}

// ---------------------------------------------------------------------------
// Kernel 2: implicit-GEMM conv via mma.sync bf16 (2-term split, 3 streams)
// grid = (98, 32, 2), block = 256, 2 CTAs/SM
// ---------------------------------------------------------------------------
extern __shared__ unsigned char smem[];

__global__ __launch_bounds__(256, 2)
void conv_mma_kernel(const float* __restrict__ in,
                     const float* __restrict__ bias,
                     float* __restrict__ out) {
    const int tid = threadIdx.x;
    const int wid = tid >> 5;
    const int lid = tid & 31;
    const int wm  = wid & 1;           // M half (64 oc)
    const int wn  = wid >> 1;          // N quarter (32 px)

    const int n   = blockIdx.y;
    const int ocg = blockIdx.z;
    const int h0  = (blockIdx.x / 7) * TH;
    const int w0  = (blockIdx.x % 7) * TW;

    const uint32_t sb = smem_u32(smem);

    // ---- accumulators, bias-initialized ----
    float acc[4][4][4];
    {
        const int r0 = lid >> 2;
#pragma unroll
        for (int mt = 0; mt < 4; ++mt) {
            const int oc0 = ocg * 128 + wm * 64 + mt * 16 + r0;
            const float b0 = __ldg(&bias[oc0]);
            const float b1 = __ldg(&bias[oc0 + 8]);
#pragma unroll
            for (int nt = 0; nt < 4; ++nt) {
                acc[mt][nt][0] = b0; acc[mt][nt][1] = b0;
                acc[mt][nt][2] = b1; acc[mt][nt][3] = b1;
            }
        }
    }

    // ---- per-lane ldmatrix address components ----
    // A: lane -> row (l%16), 16B column select (l/16)
    const uint32_t a_row = (uint32_t)(wm * 64 + (lid & 15));
    const uint32_t a_col = (uint32_t)((lid >> 4) << 4);
    // B: lane -> n row within 16-block + k-half select
    const int nb_n   = (lid & 7) + ((lid >> 4) << 3);   // 0..15
    const uint32_t khoff = (uint32_t)(((lid >> 3) & 1) * 16);
    const int px0 = wn * 32 + nb_n;
    const int px1 = px0 + 16;
    const uint32_t bc0 = (uint32_t)(((px0 >> 4) * 18 + (px0 & 15)) * P_CELL) + khoff;
    const uint32_t bc1 = (uint32_t)(((px1 >> 4) * 18 + (px1 & 15)) * P_CELL) + khoff;

    const float* inb = in + (size_t)n * CIN * HH * WW;

    for (int cblk = 0; cblk < 2; ++cblk) {
        __syncthreads();   // previous cblk done reading patches

        // ---- build split/transposed patch: pHi/pLo[y][x][c], 144B cells ----
        for (int i = tid; i < 64 * 180; i += 256) {
            const int c = i / 180;
            const int r = i - c * 180;
            const int y = r / 18;
            const int x = r - y * 18;
            const int gy = h0 - 1 + y;
            const int gx = w0 - 1 + x;
            float v = 0.0f;
            if (gy >= 0 && gy < HH && gx >= 0 && gx < WW)
                v = inb[((size_t)(cblk * 64 + c) * HH + gy) * WW + gx];
            __nv_bfloat16 h, l;
            split_bf16(v, h, l);
            const uint32_t cell = (uint32_t)((y * 18 + x) * P_CELL + c * 2);
            *(__nv_bfloat16*)(smem + S_PHI + cell) = h;
            *(__nv_bfloat16*)(smem + S_PLO + cell) = l;
        }

        for (int tap = 0; tap < 9; ++tap) {
            __syncthreads();   // A buffer free (also covers patch-build for tap 0)

            // ---- pull pre-split A tiles (hi+lo 32KB) via cp.async ----
            {
                const unsigned char* src = g_wA +
                    (size_t)(((ocg * 2 + cblk) * 9 + tap)) * (2 * A_TILE);
#pragma unroll
                for (int q = 0; q < 8; ++q)
                    cpasync16(sb + S_AHI + tid * 16 + q * 4096,
                              src + tid * 16 + q * 4096);
                asm volatile("cp.async.commit_group;" ::: "memory");
                asm volatile("cp.async.wait_group 0;" ::: "memory");
            }
            __syncthreads();

            const int kh = tap / 3, kw = tap - kh * 3;
            const uint32_t toff = (uint32_t)((kh * 18 + kw) * P_CELL);
            const uint32_t bhi_base = sb + S_PHI + toff;
            const uint32_t blo_base = sb + S_PLO + toff;

#pragma unroll
            for (int k16 = 0; k16 < 4; ++k16) {
                const uint32_t kb = (uint32_t)(k16 * 32);

                // A hi fragments (4 x ldmatrix.x4)
                uint32_t ah[4][4];
#pragma unroll
                for (int mt = 0; mt < 4; ++mt)
                    ldsm4(ah[mt], sb + S_AHI +
                          swz128((a_row + mt * 16) * 128 + kb + a_col));

                // B hi fragments (2 x ldmatrix.x4 -> 4 n8 frags)
                uint32_t bh[8];
                ldsm4(bh,     bhi_base + bc0 + kb);
                ldsm4(bh + 4, bhi_base + bc1 + kb);

                // stream 1: Ahi * Bhi
#pragma unroll
                for (int mt = 0; mt < 4; ++mt)
#pragma unroll
                    for (int nt = 0; nt < 4; ++nt)
                        mma16816(acc[mt][nt], ah[mt], bh + nt * 2);

                // B lo fragments
                uint32_t bl[8];
                ldsm4(bl,     blo_base + bc0 + kb);
                ldsm4(bl + 4, blo_base + bc1 + kb);

                // stream 2: Ahi * Blo
#pragma unroll
                for (int mt = 0; mt < 4; ++mt)
#pragma unroll
                    for (int nt = 0; nt < 4; ++nt)
                        mma16816(acc[mt][nt], ah[mt], bl + nt * 2);

                // A lo fragments
                uint32_t al[4][4];
#pragma unroll
                for (int mt = 0; mt < 4; ++mt)
                    ldsm4(al[mt], sb + S_ALO +
                          swz128((a_row + mt * 16) * 128 + kb + a_col));

                // stream 3: Alo * Bhi
#pragma unroll
                for (int mt = 0; mt < 4; ++mt)
#pragma unroll
                    for (int nt = 0; nt < 4; ++nt)
                        mma16816(acc[mt][nt], al[mt], bh + nt * 2);
            }
        }
    }

    // ---- epilogue: direct register -> global stores ----
    {
        const int r0 = lid >> 2;
        const int cp = (lid & 3) * 2;
#pragma unroll
        for (int mt = 0; mt < 4; ++mt) {
            const int oc0 = ocg * 128 + wm * 64 + mt * 16 + r0;
            float* ob0 = out + (((size_t)n * COUT + oc0) * HH + h0) * WW + w0;
            float* ob1 = ob0 + (size_t)8 * HH * WW;
#pragma unroll
            for (int nt = 0; nt < 4; ++nt) {
                const int px = wn * 32 + nt * 8 + cp;
                const int py = px >> 4;
                const int pw = px & 15;
                const size_t o = (size_t)py * WW + pw;
                *(float2*)(ob0 + o) = make_float2(acc[mt][nt][0], acc[mt][nt][1]);
                *(float2*)(ob1 + o) = make_float2(acc[mt][nt][2], acc[mt][nt][3]);
            }
        }
    }
}

// ---------------------------------------------------------------------------
// Launch
// ---------------------------------------------------------------------------
extern "C" void kernel_launch(void* const* d_in, const int* in_sizes, int n_in,
                              void* d_out, int out_size) {
    const float* input  = (const float*)d_in[0];   // (32,128,112,112)
    const float* weight = (const float*)d_in[1];   // (256,128,3,3)
    const float* bias   = (const float*)d_in[2];   // (256,)
    float* out = (float*)d_out;                    // (32,256,112,112)

    static bool configured = false;
    if (!configured) {
        cudaFuncSetAttribute(conv_mma_kernel,
                             cudaFuncAttributeMaxDynamicSharedMemorySize,
                             S_TOTAL);
        configured = true;
    }

    wprep_kernel<<<(256 * 9 * 64 + 255) / 256, 256>>>(weight);

    dim3 grid(14 * 7, NB, 2);
    conv_mma_kernel<<<grid, 256, S_TOTAL>>>(input, bias, out);
}

// round 7
// speedup vs baseline: 3.6704x; 1.3697x over previous
#include <cuda_runtime.h>
#include <cuda_fp16.h>
#include <cstdint>

// Problem constants
#define NB    32
#define CIN   128
#define HH    112
#define WW    112
#define COUT  256
#define TH    8
#define TW    16

// SMEM layout (dynamic)
#define A_TILE   16384              // 128 oc x 64 c fp16, SW128-swizzled
#define P_CELL   144                // bytes per (y,x) cell: 64ch*2B + 16B pad
#define P_BYTES  (180 * P_CELL)     // 10*18 cells = 25920 B
#define S_A0     0
#define S_A1     16384
#define S_PHI    32768
#define S_PLO    (32768 + P_BYTES)
#define S_TOTAL  (32768 + 2 * P_BYTES)   // 84608 -> 2 CTAs/SM

// Pre-rounded fp16 weights: [ocg(2)][cblk(2)][tap(9)] 16KB tiles, SW128-swizzled
__device__ unsigned char g_wA[2 * 2 * 9 * A_TILE];   // 576 KB

// ---------------------------------------------------------------------------
// Helpers
// ---------------------------------------------------------------------------
__device__ __forceinline__ uint32_t swz128(uint32_t off) {
    return off ^ ((off >> 3) & 0x70);
}
__device__ __forceinline__ uint32_t smem_u32(const void* p) {
    uint32_t a;
    asm("{ .reg .u64 t; cvta.to.shared.u64 t, %1; cvt.u32.u64 %0, t; }"
        : "=r"(a) : "l"(p));
    return a;
}
__device__ __forceinline__ void ldsm4(uint32_t* r, uint32_t addr) {
    asm volatile("ldmatrix.sync.aligned.m8n8.x4.shared.b16 {%0,%1,%2,%3}, [%4];"
                 : "=r"(r[0]), "=r"(r[1]), "=r"(r[2]), "=r"(r[3]) : "r"(addr));
}
__device__ __forceinline__ void mma16816(float* d, const uint32_t* a,
                                         const uint32_t* b) {
    asm volatile(
        "mma.sync.aligned.m16n8k16.row.col.f32.f16.f16.f32 "
        "{%0,%1,%2,%3}, {%4,%5,%6,%7}, {%8,%9}, {%0,%1,%2,%3};"
        : "+f"(d[0]), "+f"(d[1]), "+f"(d[2]), "+f"(d[3])
        : "r"(a[0]), "r"(a[1]), "r"(a[2]), "r"(a[3]), "r"(b[0]), "r"(b[1]));
}
__device__ __forceinline__ void cpasync16(uint32_t dst, const void* src) {
    asm volatile("cp.async.cg.shared.global [%0], [%1], 16;"
                 :: "r"(dst), "l"(src) : "memory");
}
__device__ __forceinline__ void split_fp16(float v, __half& h, __half& l) {
    h = __float2half_rn(v);
    l = __float2half_rn(v - __half2float(h));
}

// ---------------------------------------------------------------------------
// Kernel 1: round weights to fp16 tiles [ocg][cblk][tap], SW128-swizzled.
// Tile layout: row = oc_local (128B rows of 64 fp16 channel values).
// ---------------------------------------------------------------------------
__global__ void wprep_kernel(const float* __restrict__ w) {
    int j = blockIdx.x * blockDim.x + threadIdx.x;   // 256 oc * 9 tap * 64 cpair
    if (j >= 256 * 9 * 64) return;
    int cpair = j & 63;
    int tap   = (j >> 6) % 9;
    int oc    = j / 576;
    int c     = cpair * 2;
    int ocg   = oc >> 7, ocl = oc & 127;
    int cblk  = c >> 6,  cl  = c & 63;

    __half h0 = __float2half_rn(w[((size_t)oc * CIN + c) * 9 + tap]);
    __half h1 = __float2half_rn(w[((size_t)oc * CIN + c + 1) * 9 + tap]);
    uint32_t hi = (uint32_t)__half_as_ushort(h0) |
                  ((uint32_t)__half_as_ushort(h1) << 16);

    size_t base = (size_t)(((ocg * 2 + cblk) * 9 + tap)) * A_TILE;
    uint32_t off = swz128((uint32_t)(ocl * 128 + cl * 2));
    *(uint32_t*)(g_wA + base + off) = hi;
}

// ---------------------------------------------------------------------------
// Kernel 2: implicit-GEMM conv, fp16 2-stream (A rounded, B split hi/lo),
// double-buffered cp.async weight pipeline.
// grid = (98, 32, 2), block = 256, 2 CTAs/SM
// ---------------------------------------------------------------------------
extern __shared__ unsigned char smem[];

__global__ __launch_bounds__(256, 2)
void conv_mma_kernel(const float* __restrict__ in,
                     const float* __restrict__ bias,
                     float* __restrict__ out) {
    const int tid = threadIdx.x;
    const int wid = tid >> 5;
    const int lid = tid & 31;
    const int wm  = wid & 1;           // M half (64 oc)
    const int wn  = wid >> 1;          // N quarter (32 px)

    const int n   = blockIdx.y;
    const int ocg = blockIdx.z;
    const int h0  = (blockIdx.x / 7) * TH;
    const int w0  = (blockIdx.x % 7) * TW;

    const uint32_t sb = smem_u32(smem);

    // ---- accumulators, bias-initialized ----
    float acc[4][4][4];
    {
        const int r0 = lid >> 2;
#pragma unroll
        for (int mt = 0; mt < 4; ++mt) {
            const int oc0 = ocg * 128 + wm * 64 + mt * 16 + r0;
            const float b0 = __ldg(&bias[oc0]);
            const float b1 = __ldg(&bias[oc0 + 8]);
#pragma unroll
            for (int nt = 0; nt < 4; ++nt) {
                acc[mt][nt][0] = b0; acc[mt][nt][1] = b0;
                acc[mt][nt][2] = b1; acc[mt][nt][3] = b1;
            }
        }
    }

    // ---- per-lane ldmatrix address components (identical to validated R6) ----
    const uint32_t a_row = (uint32_t)(wm * 64 + (lid & 15));
    const uint32_t a_col = (uint32_t)((lid >> 4) << 4);
    const int nb_n   = (lid & 7) + ((lid >> 4) << 3);
    const uint32_t khoff = (uint32_t)(((lid >> 3) & 1) * 16);
    const int px0 = wn * 32 + nb_n;
    const int px1 = px0 + 16;
    const uint32_t bc0 = (uint32_t)(((px0 >> 4) * 18 + (px0 & 15)) * P_CELL) + khoff;
    const uint32_t bc1 = (uint32_t)(((px1 >> 4) * 18 + (px1 & 15)) * P_CELL) + khoff;

    const float* inb = in + (size_t)n * CIN * HH * WW;

    // ---- A-tile prefetch (16KB per tap, double-buffered) ----
    auto prefetchA = [&](int j) {
        const unsigned char* src =
            g_wA + (size_t)((ocg * 2 + (j / 9)) * 9 + (j % 9)) * A_TILE;
        const uint32_t dst = sb + (uint32_t)((j & 1) * A_TILE);
#pragma unroll
        for (int q = 0; q < 4; ++q)
            cpasync16(dst + tid * 16 + q * 4096, src + tid * 16 + q * 4096);
        asm volatile("cp.async.commit_group;" ::: "memory");
    };

    prefetchA(0);

    for (int cblk = 0; cblk < 2; ++cblk) {
        __syncthreads();   // prior cblk's MMAs done reading patch

        // ---- build split fp16 patch: pHi/pLo[y][x][c], 144B cells ----
        for (int i = tid; i < 64 * 180; i += 256) {
            const int c = i / 180;
            const int r = i - c * 180;
            const int y = r / 18;
            const int x = r - y * 18;
            const int gy = h0 - 1 + y;
            const int gx = w0 - 1 + x;
            float v = 0.0f;
            if (gy >= 0 && gy < HH && gx >= 0 && gx < WW)
                v = inb[((size_t)(cblk * 64 + c) * HH + gy) * WW + gx];
            __half h, l;
            split_fp16(v, h, l);
            const uint32_t cell = (uint32_t)((y * 18 + x) * P_CELL + c * 2);
            *(__half*)(smem + S_PHI + cell) = h;
            *(__half*)(smem + S_PLO + cell) = l;
        }

        for (int tap = 0; tap < 9; ++tap) {
            const int j = cblk * 9 + tap;

            // prefetch next tile, then wait for the current one
            if (j < 17) {
                prefetchA(j + 1);
                asm volatile("cp.async.wait_group 1;" ::: "memory");
            } else {
                asm volatile("cp.async.wait_group 0;" ::: "memory");
            }
            __syncthreads();   // A[j] visible; patch built (covers tap 0)

            const uint32_t abuf = sb + (uint32_t)((j & 1) * A_TILE);
            const int kh = tap / 3, kw = tap - kh * 3;
            const uint32_t toff = (uint32_t)((kh * 18 + kw) * P_CELL);
            const uint32_t bhi_base = sb + S_PHI + toff;
            const uint32_t blo_base = sb + S_PLO + toff;

#pragma unroll
            for (int k16 = 0; k16 < 4; ++k16) {
                const uint32_t kb = (uint32_t)(k16 * 32);

                // A fragments (weights, single fp16)
                uint32_t ah[4][4];
#pragma unroll
                for (int mt = 0; mt < 4; ++mt)
                    ldsm4(ah[mt], abuf +
                          swz128((a_row + mt * 16) * 128 + kb + a_col));

                // B hi fragments
                uint32_t bh[8];
                ldsm4(bh,     bhi_base + bc0 + kb);
                ldsm4(bh + 4, bhi_base + bc1 + kb);

                // stream 1: A * Bhi
#pragma unroll
                for (int mt = 0; mt < 4; ++mt)
#pragma unroll
                    for (int nt = 0; nt < 4; ++nt)
                        mma16816(acc[mt][nt], ah[mt], bh + nt * 2);

                // B lo fragments
                uint32_t bl[8];
                ldsm4(bl,     blo_base + bc0 + kb);
                ldsm4(bl + 4, blo_base + bc1 + kb);

                // stream 2: A * Blo
#pragma unroll
                for (int mt = 0; mt < 4; ++mt)
#pragma unroll
                    for (int nt = 0; nt < 4; ++nt)
                        mma16816(acc[mt][nt], ah[mt], bl + nt * 2);
            }
            __syncthreads();   // release A buf j before prefetch j+2 overwrites
        }
    }

    // ---- epilogue: direct register -> global stores ----
    {
        const int r0 = lid >> 2;
        const int cp = (lid & 3) * 2;
#pragma unroll
        for (int mt = 0; mt < 4; ++mt) {
            const int oc0 = ocg * 128 + wm * 64 + mt * 16 + r0;
            float* ob0 = out + (((size_t)n * COUT + oc0) * HH + h0) * WW + w0;
            float* ob1 = ob0 + (size_t)8 * HH * WW;
#pragma unroll
            for (int nt = 0; nt < 4; ++nt) {
                const int px = wn * 32 + nt * 8 + cp;
                const int py = px >> 4;
                const int pw = px & 15;
                const size_t o = (size_t)py * WW + pw;
                *(float2*)(ob0 + o) = make_float2(acc[mt][nt][0], acc[mt][nt][1]);
                *(float2*)(ob1 + o) = make_float2(acc[mt][nt][2], acc[mt][nt][3]);
            }
        }
    }
}

// ---------------------------------------------------------------------------
// Launch
// ---------------------------------------------------------------------------
extern "C" void kernel_launch(void* const* d_in, const int* in_sizes, int n_in,
                              void* d_out, int out_size) {
    const float* input  = (const float*)d_in[0];   // (32,128,112,112)
    const float* weight = (const float*)d_in[1];   // (256,128,3,3)
    const float* bias   = (const float*)d_in[2];   // (256,)
    float* out = (float*)d_out;                    // (32,256,112,112)

    static bool configured = false;
    if (!configured) {
        cudaFuncSetAttribute(conv_mma_kernel,
                             cudaFuncAttributeMaxDynamicSharedMemorySize,
                             S_TOTAL);
        configured = true;
    }

    wprep_kernel<<<(256 * 9 * 64 + 255) / 256, 256>>>(weight);

    dim3 grid(14 * 7, NB, 2);
    conv_mma_kernel<<<grid, 256, S_TOTAL>>>(input, bias, out);
}

// round 8
// speedup vs baseline: 5.4283x; 1.4789x over previous
#include <cuda_runtime.h>
#include <cuda_fp16.h>
#include <cstdint>

// Problem constants
#define NB    32
#define CIN   128
#define HH    112
#define WW    112
#define COUT  256
#define TH    8
#define TW    16

// SMEM layout (dynamic)
#define A_TILE   16384              // 128 oc x 64 c fp16, SW128-swizzled
#define NBUF     3                  // A-tile ring depth
#define P_CELL   144                // bytes per (y,x) cell: 64ch*2B + 16B pad
#define P_BYTES  (180 * P_CELL)     // 10*18 cells = 25920 B
#define S_P      (NBUF * A_TILE)    // 49152
#define S_TOTAL  (S_P + P_BYTES)    // 75072 -> 2 CTAs/SM

// Pre-rounded fp16 weights: [ocg(2)][cblk(2)][tap(9)] 16KB tiles, SW128-swizzled
__device__ unsigned char g_wA[2 * 2 * 9 * A_TILE];   // 576 KB

// ---------------------------------------------------------------------------
// Helpers
// ---------------------------------------------------------------------------
__device__ __forceinline__ uint32_t swz128(uint32_t off) {
    return off ^ ((off >> 3) & 0x70);
}
__device__ __forceinline__ uint32_t smem_u32(const void* p) {
    uint32_t a;
    asm("{ .reg .u64 t; cvta.to.shared.u64 t, %1; cvt.u32.u64 %0, t; }"
        : "=r"(a) : "l"(p));
    return a;
}
__device__ __forceinline__ void ldsm4(uint32_t* r, uint32_t addr) {
    asm volatile("ldmatrix.sync.aligned.m8n8.x4.shared.b16 {%0,%1,%2,%3}, [%4];"
                 : "=r"(r[0]), "=r"(r[1]), "=r"(r[2]), "=r"(r[3]) : "r"(addr));
}
__device__ __forceinline__ void mma16816(float* d, const uint32_t* a,
                                         const uint32_t* b) {
    asm volatile(
        "mma.sync.aligned.m16n8k16.row.col.f32.f16.f16.f32 "
        "{%0,%1,%2,%3}, {%4,%5,%6,%7}, {%8,%9}, {%0,%1,%2,%3};"
        : "+f"(d[0]), "+f"(d[1]), "+f"(d[2]), "+f"(d[3])
        : "r"(a[0]), "r"(a[1]), "r"(a[2]), "r"(a[3]), "r"(b[0]), "r"(b[1]));
}
__device__ __forceinline__ void cpasync16(uint32_t dst, const void* src) {
    asm volatile("cp.async.cg.shared.global [%0], [%1], 16;"
                 :: "r"(dst), "l"(src) : "memory");
}

// ---------------------------------------------------------------------------
// Kernel 1: round weights to fp16 tiles [ocg][cblk][tap], SW128-swizzled.
// ---------------------------------------------------------------------------
__global__ void wprep_kernel(const float* __restrict__ w) {
    int j = blockIdx.x * blockDim.x + threadIdx.x;   // 256 oc * 9 tap * 64 cpair
    if (j >= 256 * 9 * 64) return;
    int cpair = j & 63;
    int tap   = (j >> 6) % 9;
    int oc    = j / 576;
    int c     = cpair * 2;
    int ocg   = oc >> 7, ocl = oc & 127;
    int cblk  = c >> 6,  cl  = c & 63;

    __half h0 = __float2half_rn(w[((size_t)oc * CIN + c) * 9 + tap]);
    __half h1 = __float2half_rn(w[((size_t)oc * CIN + c + 1) * 9 + tap]);
    uint32_t hi = (uint32_t)__half_as_ushort(h0) |
                  ((uint32_t)__half_as_ushort(h1) << 16);

    size_t base = (size_t)(((ocg * 2 + cblk) * 9 + tap)) * A_TILE;
    uint32_t off = swz128((uint32_t)(ocl * 128 + cl * 2));
    *(uint32_t*)(g_wA + base + off) = hi;
}

// ---------------------------------------------------------------------------
// Kernel 2: implicit-GEMM conv, single-stream fp16 MMA,
// triple-buffered cp.async weight ring (1 barrier per tap).
// grid = (98, 32, 2), block = 256, 2 CTAs/SM
// ---------------------------------------------------------------------------
extern __shared__ unsigned char smem[];

__global__ __launch_bounds__(256, 2)
void conv_mma_kernel(const float* __restrict__ in,
                     const float* __restrict__ bias,
                     float* __restrict__ out) {
    const int tid = threadIdx.x;
    const int wid = tid >> 5;
    const int lid = tid & 31;
    const int wm  = wid & 1;           // M half (64 oc)
    const int wn  = wid >> 1;          // N quarter (32 px)

    const int n   = blockIdx.y;
    const int ocg = blockIdx.z;
    const int h0  = (blockIdx.x / 7) * TH;
    const int w0  = (blockIdx.x % 7) * TW;

    const uint32_t sb = smem_u32(smem);

    // ---- accumulators, bias-initialized ----
    float acc[4][4][4];
    {
        const int r0 = lid >> 2;
#pragma unroll
        for (int mt = 0; mt < 4; ++mt) {
            const int oc0 = ocg * 128 + wm * 64 + mt * 16 + r0;
            const float b0 = __ldg(&bias[oc0]);
            const float b1 = __ldg(&bias[oc0 + 8]);
#pragma unroll
            for (int nt = 0; nt < 4; ++nt) {
                acc[mt][nt][0] = b0; acc[mt][nt][1] = b0;
                acc[mt][nt][2] = b1; acc[mt][nt][3] = b1;
            }
        }
    }

    // ---- per-lane ldmatrix address components (validated in R6/R7) ----
    const uint32_t a_row = (uint32_t)(wm * 64 + (lid & 15));
    const uint32_t a_col = (uint32_t)((lid >> 4) << 4);
    const int nb_n   = (lid & 7) + ((lid >> 4) << 3);
    const uint32_t khoff = (uint32_t)(((lid >> 3) & 1) * 16);
    const int px0 = wn * 32 + nb_n;
    const int px1 = px0 + 16;
    const uint32_t bc0 = (uint32_t)(((px0 >> 4) * 18 + (px0 & 15)) * P_CELL) + khoff;
    const uint32_t bc1 = (uint32_t)(((px1 >> 4) * 18 + (px1 & 15)) * P_CELL) + khoff;

    const float* inb = in + (size_t)n * CIN * HH * WW;

    // ---- A-tile prefetch (16KB per tap, 3-deep ring) ----
    auto prefetchA = [&](int j) {
        const unsigned char* src =
            g_wA + (size_t)((ocg * 2 + (j / 9)) * 9 + (j % 9)) * A_TILE;
        const uint32_t dst = sb + (uint32_t)((j % NBUF) * A_TILE);
#pragma unroll
        for (int q = 0; q < 4; ++q)
            cpasync16(dst + tid * 16 + q * 4096, src + tid * 16 + q * 4096);
        asm volatile("cp.async.commit_group;" ::: "memory");
    };

    prefetchA(0);
    prefetchA(1);

    for (int cblk = 0; cblk < 2; ++cblk) {
        __syncthreads();   // prior cblk's MMAs done reading patch

        // ---- build fp16 patch: p[y][x][c], 144B cells ----
        for (int i = tid; i < 64 * 180; i += 256) {
            const int c = i / 180;
            const int r = i - c * 180;
            const int y = r / 18;
            const int x = r - y * 18;
            const int gy = h0 - 1 + y;
            const int gx = w0 - 1 + x;
            float v = 0.0f;
            if (gy >= 0 && gy < HH && gx >= 0 && gx < WW)
                v = inb[((size_t)(cblk * 64 + c) * HH + gy) * WW + gx];
            const uint32_t cell = (uint32_t)((y * 18 + x) * P_CELL + c * 2);
            *(__half*)(smem + S_P + cell) = __float2half_rn(v);
        }

        for (int tap = 0; tap < 9; ++tap) {
            const int j = cblk * 9 + tap;

            // wait for A[j]; newest committed group is j+1 (except at the end)
            if (j < 17)
                asm volatile("cp.async.wait_group 1;" ::: "memory");
            else
                asm volatile("cp.async.wait_group 0;" ::: "memory");
            __syncthreads();   // A[j] visible to all; buffer (j+2)%3 released;
                               // also orders patch build for tap 0

            if (j + 2 <= 17) prefetchA(j + 2);

            const uint32_t abuf = sb + (uint32_t)((j % NBUF) * A_TILE);
            const int kh = tap / 3, kw = tap - kh * 3;
            const uint32_t toff = (uint32_t)((kh * 18 + kw) * P_CELL);
            const uint32_t b_base = sb + S_P + toff;

#pragma unroll
            for (int k16 = 0; k16 < 4; ++k16) {
                const uint32_t kb = (uint32_t)(k16 * 32);

                // A fragments (weights)
                uint32_t af[4][4];
#pragma unroll
                for (int mt = 0; mt < 4; ++mt)
                    ldsm4(af[mt], abuf +
                          swz128((a_row + mt * 16) * 128 + kb + a_col));

                // B fragments (inputs)
                uint32_t bf[8];
                ldsm4(bf,     b_base + bc0 + kb);
                ldsm4(bf + 4, b_base + bc1 + kb);

#pragma unroll
                for (int mt = 0; mt < 4; ++mt)
#pragma unroll
                    for (int nt = 0; nt < 4; ++nt)
                        mma16816(acc[mt][nt], af[mt], bf + nt * 2);
            }
        }
    }

    // ---- epilogue: direct register -> global stores ----
    {
        const int r0 = lid >> 2;
        const int cp = (lid & 3) * 2;
#pragma unroll
        for (int mt = 0; mt < 4; ++mt) {
            const int oc0 = ocg * 128 + wm * 64 + mt * 16 + r0;
            float* ob0 = out + (((size_t)n * COUT + oc0) * HH + h0) * WW + w0;
            float* ob1 = ob0 + (size_t)8 * HH * WW;
#pragma unroll
            for (int nt = 0; nt < 4; ++nt) {
                const int px = wn * 32 + nt * 8 + cp;
                const int py = px >> 4;
                const int pw = px & 15;
                const size_t o = (size_t)py * WW + pw;
                *(float2*)(ob0 + o) = make_float2(acc[mt][nt][0], acc[mt][nt][1]);
                *(float2*)(ob1 + o) = make_float2(acc[mt][nt][2], acc[mt][nt][3]);
            }
        }
    }
}

// ---------------------------------------------------------------------------
// Launch
// ---------------------------------------------------------------------------
extern "C" void kernel_launch(void* const* d_in, const int* in_sizes, int n_in,
                              void* d_out, int out_size) {
    const float* input  = (const float*)d_in[0];   // (32,128,112,112)
    const float* weight = (const float*)d_in[1];   // (256,128,3,3)
    const float* bias   = (const float*)d_in[2];   // (256,)
    float* out = (float*)d_out;                    // (32,256,112,112)

    static bool configured = false;
    if (!configured) {
        cudaFuncSetAttribute(conv_mma_kernel,
                             cudaFuncAttributeMaxDynamicSharedMemorySize,
                             S_TOTAL);
        configured = true;
    }

    wprep_kernel<<<(256 * 9 * 64 + 255) / 256, 256>>>(weight);

    dim3 grid(14 * 7, NB, 2);
    conv_mma_kernel<<<grid, 256, S_TOTAL>>>(input, bias, out);
}

// round 9
// speedup vs baseline: 5.7125x; 1.0524x over previous
#include <cuda_runtime.h>
#include <cuda_fp16.h>
#include <cstdint>

// Problem constants
#define NB    32
#define CIN   128
#define HH    112
#define WW    112
#define COUT  256
#define TH    8
#define TW    16

// SMEM layout (dynamic)
#define A_TILE   16384              // 128 oc x 64 c fp16, SW128-swizzled
#define NBUF     2                  // A-tile ring depth
#define P_CELL   144                // bytes per (y,x) cell: 64ch*2B + 16B pad
#define P_BYTES  (180 * P_CELL)     // 10*18 cells = 25920 B
#define S_P0     (NBUF * A_TILE)    // 32768
#define S_P1     (S_P0 + P_BYTES)   // 58688
#define S_TOTAL  (S_P1 + P_BYTES)   // 84608 -> 2 CTAs/SM

// Pre-rounded fp16 weights: [ocg(2)][cblk(2)][tap(9)] 16KB tiles, SW128-swizzled
__device__ unsigned char g_wA[2 * 2 * 9 * A_TILE];   // 576 KB

// ---------------------------------------------------------------------------
// Helpers
// ---------------------------------------------------------------------------
__device__ __forceinline__ uint32_t swz128(uint32_t off) {
    return off ^ ((off >> 3) & 0x70);
}
__device__ __forceinline__ uint32_t smem_u32(const void* p) {
    uint32_t a;
    asm("{ .reg .u64 t; cvta.to.shared.u64 t, %1; cvt.u32.u64 %0, t; }"
        : "=r"(a) : "l"(p));
    return a;
}
__device__ __forceinline__ void ldsm4(uint32_t* r, uint32_t addr) {
    asm volatile("ldmatrix.sync.aligned.m8n8.x4.shared.b16 {%0,%1,%2,%3}, [%4];"
                 : "=r"(r[0]), "=r"(r[1]), "=r"(r[2]), "=r"(r[3]) : "r"(addr));
}
__device__ __forceinline__ void mma16816(float* d, const uint32_t* a,
                                         const uint32_t* b) {
    asm volatile(
        "mma.sync.aligned.m16n8k16.row.col.f32.f16.f16.f32 "
        "{%0,%1,%2,%3}, {%4,%5,%6,%7}, {%8,%9}, {%0,%1,%2,%3};"
        : "+f"(d[0]), "+f"(d[1]), "+f"(d[2]), "+f"(d[3])
        : "r"(a[0]), "r"(a[1]), "r"(a[2]), "r"(a[3]), "r"(b[0]), "r"(b[1]));
}
__device__ __forceinline__ void cpasync16(uint32_t dst, const void* src) {
    asm volatile("cp.async.cg.shared.global [%0], [%1], 16;"
                 :: "r"(dst), "l"(src) : "memory");
}

// ---------------------------------------------------------------------------
// Kernel 1: round weights to fp16 tiles [ocg][cblk][tap], SW128-swizzled.
// ---------------------------------------------------------------------------
__global__ void wprep_kernel(const float* __restrict__ w) {
    int j = blockIdx.x * blockDim.x + threadIdx.x;   // 256 oc * 9 tap * 64 cpair
    if (j >= 256 * 9 * 64) return;
    int cpair = j & 63;
    int tap   = (j >> 6) % 9;
    int oc    = j / 576;
    int c     = cpair * 2;
    int ocg   = oc >> 7, ocl = oc & 127;
    int cblk  = c >> 6,  cl  = c & 63;

    __half h0 = __float2half_rn(w[((size_t)oc * CIN + c) * 9 + tap]);
    __half h1 = __float2half_rn(w[((size_t)oc * CIN + c + 1) * 9 + tap]);
    uint32_t hi = (uint32_t)__half_as_ushort(h0) |
                  ((uint32_t)__half_as_ushort(h1) << 16);

    size_t base = (size_t)(((ocg * 2 + cblk) * 9 + tap)) * A_TILE;
    uint32_t off = swz128((uint32_t)(ocl * 128 + cl * 2));
    *(uint32_t*)(g_wA + base + off) = hi;
}

// ---------------------------------------------------------------------------
// Kernel 2: implicit-GEMM conv, single-stream fp16 MMA.
// Double-buffered patch: cblk1's patch is built incrementally UNDER cblk0's
// MMA taps (5 elements/thread/tap; LDG issued at tap top, STS after MMAs).
// A-tile ring depth 2, prefetch distance 1.
// grid = (98, 32, 2), block = 256, 2 CTAs/SM
// ---------------------------------------------------------------------------
extern __shared__ unsigned char smem[];

__global__ __launch_bounds__(256, 2)
void conv_mma_kernel(const float* __restrict__ in,
                     const float* __restrict__ bias,
                     float* __restrict__ out) {
    const int tid = threadIdx.x;
    const int wid = tid >> 5;
    const int lid = tid & 31;
    const int wm  = wid & 1;           // M half (64 oc)
    const int wn  = wid >> 1;          // N quarter (32 px)

    const int n   = blockIdx.y;
    const int ocg = blockIdx.z;
    const int h0  = (blockIdx.x / 7) * TH;
    const int w0  = (blockIdx.x % 7) * TW;

    const uint32_t sb = smem_u32(smem);

    // ---- accumulators, bias-initialized ----
    float acc[4][4][4];
    {
        const int r0 = lid >> 2;
#pragma unroll
        for (int mt = 0; mt < 4; ++mt) {
            const int oc0 = ocg * 128 + wm * 64 + mt * 16 + r0;
            const float b0 = __ldg(&bias[oc0]);
            const float b1 = __ldg(&bias[oc0 + 8]);
#pragma unroll
            for (int nt = 0; nt < 4; ++nt) {
                acc[mt][nt][0] = b0; acc[mt][nt][1] = b0;
                acc[mt][nt][2] = b1; acc[mt][nt][3] = b1;
            }
        }
    }

    // ---- per-lane ldmatrix address components (validated R6-R8) ----
    const uint32_t a_row = (uint32_t)(wm * 64 + (lid & 15));
    const uint32_t a_col = (uint32_t)((lid >> 4) << 4);
    const int nb_n   = (lid & 7) + ((lid >> 4) << 3);
    const uint32_t khoff = (uint32_t)(((lid >> 3) & 1) * 16);
    const int px0 = wn * 32 + nb_n;
    const int px1 = px0 + 16;
    const uint32_t bc0 = (uint32_t)(((px0 >> 4) * 18 + (px0 & 15)) * P_CELL) + khoff;
    const uint32_t bc1 = (uint32_t)(((px1 >> 4) * 18 + (px1 & 15)) * P_CELL) + khoff;

    const float* inb = in + (size_t)n * CIN * HH * WW;

    // one patch element: index i (< 64*180) of channel block cb -> (value, cell)
    auto ld_elem = [&](int i, int cb) -> float {
        const int c = i / 180;
        const int r = i - c * 180;
        const int y = r / 18;
        const int x = r - y * 18;
        const int gy = h0 - 1 + y;
        const int gx = w0 - 1 + x;
        float v = 0.0f;
        if (gy >= 0 && gy < HH && gx >= 0 && gx < WW)
            v = __ldg(&inb[((size_t)(cb * 64 + c) * HH + gy) * WW + gx]);
        return v;
    };
    auto cell_of = [&](int i) -> uint32_t {
        const int c = i / 180;
        const int r = i - c * 180;
        return (uint32_t)(r * P_CELL + c * 2);
    };

    // ---- A-tile prefetch (16KB per tap, 2-deep ring) ----
    auto prefetchA = [&](int j) {
        const unsigned char* src =
            g_wA + (size_t)((ocg * 2 + (j / 9)) * 9 + (j % 9)) * A_TILE;
        const uint32_t dst = sb + (uint32_t)((j & 1) * A_TILE);
#pragma unroll
        for (int q = 0; q < 4; ++q)
            cpasync16(dst + tid * 16 + q * 4096, src + tid * 16 + q * 4096);
        asm volatile("cp.async.commit_group;" ::: "memory");
    };

    prefetchA(0);   // overlaps initial patch build

    // ---- initial patch build (cblk 0), the only exposed build ----
    for (int k = 0; k < 45; ++k) {
        const int i = tid + k * 256;
        const float v = ld_elem(i, 0);
        *(__half*)(smem + S_P0 + cell_of(i)) = __float2half_rn(v);
    }

    for (int cblk = 0; cblk < 2; ++cblk) {
        const uint32_t pbase = sb + (cblk == 0 ? S_P0 : S_P1);

        for (int tap = 0; tap < 9; ++tap) {
            const int j = cblk * 9 + tap;

            // ---- early LDGs for next cblk's patch (hidden under this tap) ----
            float pv[5];
            if (cblk == 0) {
#pragma unroll
                for (int q = 0; q < 5; ++q)
                    pv[q] = ld_elem(tid + (tap * 5 + q) * 256, 1);
            }

            // wait for A[j] (its copy ran under tap j-1), sync, prefetch A[j+1]
            asm volatile("cp.async.wait_group 0;" ::: "memory");
            __syncthreads();   // A[j] visible; buf (j-1)&1 released;
                               // tap0: also orders patch writes
            if (j < 17) prefetchA(j + 1);

            const uint32_t abuf = sb + (uint32_t)((j & 1) * A_TILE);
            const int kh = tap / 3, kw = tap - kh * 3;
            const uint32_t toff = (uint32_t)((kh * 18 + kw) * P_CELL);
            const uint32_t b_base = pbase + toff;

#pragma unroll
            for (int k16 = 0; k16 < 4; ++k16) {
                const uint32_t kb = (uint32_t)(k16 * 32);

                uint32_t af[4][4];
#pragma unroll
                for (int mt = 0; mt < 4; ++mt)
                    ldsm4(af[mt], abuf +
                          swz128((a_row + mt * 16) * 128 + kb + a_col));

                uint32_t bf[8];
                ldsm4(bf,     b_base + bc0 + kb);
                ldsm4(bf + 4, b_base + bc1 + kb);

#pragma unroll
                for (int mt = 0; mt < 4; ++mt)
#pragma unroll
                    for (int nt = 0; nt < 4; ++nt)
                        mma16816(acc[mt][nt], af[mt], bf + nt * 2);
            }

            // ---- store next-cblk patch elements (LDG latency long absorbed) ----
            if (cblk == 0) {
#pragma unroll
                for (int q = 0; q < 5; ++q) {
                    const int i = tid + (tap * 5 + q) * 256;
                    *(__half*)(smem + S_P1 + cell_of(i)) = __float2half_rn(pv[q]);
                }
            }
        }
    }

    // ---- epilogue: direct register -> global stores ----
    {
        const int r0 = lid >> 2;
        const int cp = (lid & 3) * 2;
#pragma unroll
        for (int mt = 0; mt < 4; ++mt) {
            const int oc0 = ocg * 128 + wm * 64 + mt * 16 + r0;
            float* ob0 = out + (((size_t)n * COUT + oc0) * HH + h0) * WW + w0;
            float* ob1 = ob0 + (size_t)8 * HH * WW;
#pragma unroll
            for (int nt = 0; nt < 4; ++nt) {
                const int px = wn * 32 + nt * 8 + cp;
                const int py = px >> 4;
                const int pw = px & 15;
                const size_t o = (size_t)py * WW + pw;
                *(float2*)(ob0 + o) = make_float2(acc[mt][nt][0], acc[mt][nt][1]);
                *(float2*)(ob1 + o) = make_float2(acc[mt][nt][2], acc[mt][nt][3]);
            }
        }
    }
}

// ---------------------------------------------------------------------------
// Launch
// ---------------------------------------------------------------------------
extern "C" void kernel_launch(void* const* d_in, const int* in_sizes, int n_in,
                              void* d_out, int out_size) {
    const float* input  = (const float*)d_in[0];   // (32,128,112,112)
    const float* weight = (const float*)d_in[1];   // (256,128,3,3)
    const float* bias   = (const float*)d_in[2];   // (256,)
    float* out = (float*)d_out;                    // (32,256,112,112)

    static bool configured = false;
    if (!configured) {
        cudaFuncSetAttribute(conv_mma_kernel,
                             cudaFuncAttributeMaxDynamicSharedMemorySize,
                             S_TOTAL);
        configured = true;
    }

    wprep_kernel<<<(256 * 9 * 64 + 255) / 256, 256>>>(weight);

    dim3 grid(14 * 7, NB, 2);
    conv_mma_kernel<<<grid, 256, S_TOTAL>>>(input, bias, out);
}